// round 5
// baseline (speedup 1.0000x reference)
#include <cuda_runtime.h>
#include <cuda_bf16.h>

#define EPS 1e-16f
#define W 1024
#define H 1024
#define ROWS 4          // output rows per thread/block
#define TPB 256         // 256 threads * 4 px = 1024 = full row width

__global__ __launch_bounds__(TPB, 6)
void curvature_kernel(const float* __restrict__ u, float* __restrict__ out) {
    // block handles ROWS rows x full width of one batch image
    const int tile = blockIdx.x;            // b * (H/ROWS) + row-tile
    const int b    = tile >> 8;             // H/ROWS = 256 tiles per image
    const int x0   = (tile & 255) * ROWS;   // first output row
    const int y    = threadIdx.x * 4;       // first output col (float4 granule)
    const int lane = threadIdx.x & 31;

    const float* ub = u   + (size_t)b * (H * W);
    float*       ob = out + (size_t)b * (H * W);

    // ---- seam scalar loads issued FIRST so they overlap the vector loads ----
    // Only lanes 0/31 consume them; issue unconditionally costs extra traffic,
    // so keep them predicated but placed before the dependent shuffle chain.
    float seamL[ROWS + 1], seamR[ROWS + 1];
    if (lane == 0 && y != 0) {
        #pragma unroll
        for (int k = 0; k <= ROWS; ++k) {
            int r = x0 + k;                    // never < 0
            r = (r >= H) ? (H - 2) : r;
            seamL[k] = __ldg(ub + (size_t)r * W + (y - 1));
        }
    }
    if (lane == 31 && y + 4 != W) {
        #pragma unroll
        for (int k = 0; k <= ROWS; ++k) {
            int r = x0 - 1 + k;                // never >= H
            r = (r < 0) ? 1 : r;
            seamR[k] = __ldg(ub + (size_t)r * W + (y + 4));
        }
    }

    // ---- 6 row-vectors (rows x0-1 .. x0+4) at col y, reflect-clamped in x ----
    float rows[ROWS + 2][4];
    #pragma unroll
    for (int i = 0; i < ROWS + 2; ++i) {
        int r = x0 - 1 + i;
        r = (r < 0) ? 1 : ((r >= H) ? (H - 2) : r);
        float4 v = *reinterpret_cast<const float4*>(ub + (size_t)r * W + y);
        rows[i][0] = v.x; rows[i][1] = v.y; rows[i][2] = v.z; rows[i][3] = v.w;
    }

    // ---- side columns via warp shuffle (warp covers 128 contiguous cols) ----
    // lftv[k] = u[reflect(x0+k),   y-1]  == lane-1's rows[k+1][3]   k=0..ROWS
    // rgtv[k] = u[reflect(x0-1+k), y+4]  == lane+1's rows[k][0]     k=0..ROWS
    float lftv[ROWS + 1], rgtv[ROWS + 1];
    #pragma unroll
    for (int k = 0; k <= ROWS; ++k) {
        lftv[k] = __shfl_up_sync(0xffffffffu, rows[k + 1][3], 1);
        rgtv[k] = __shfl_down_sync(0xffffffffu, rows[k][0], 1);
    }
    // warp-seam / image-edge fixups (2 lanes per warp, values already in flight)
    if (lane == 0) {
        #pragma unroll
        for (int k = 0; k <= ROWS; ++k)
            lftv[k] = (y == 0) ? rows[k + 1][1] : seamL[k];   // reflect: col -1 -> 1
    }
    if (lane == 31) {
        #pragma unroll
        for (int k = 0; k <= ROWS; ++k)
            rgtv[k] = (y + 4 == W) ? rows[k][2] : seamR[k];   // reflect: col W -> W-2
    }

    // ---- compute ROWS x 4 outputs ----
    #pragma unroll
    for (int i = 0; i < ROWS; ++i) {
        float res[4];
        #pragma unroll
        for (int j = 0; j < 4; ++j) {
            const float c    = rows[i + 1][j];                        // u[x, y+j]
            const float up   = rows[i][j];                            // u[x-1, y+j]
            const float dn   = rows[i + 2][j];                        // u[x+1, y+j]
            const float rgt  = (j < 3) ? rows[i + 1][j + 1] : rgtv[i + 1]; // u[x, y+j+1]
            const float lft  = (j > 0) ? rows[i + 1][j - 1] : lftv[i];     // u[x, y+j-1]
            const float up_r = (j < 3) ? rows[i][j + 1]     : rgtv[i];     // u[x-1, y+j+1]
            const float dn_l = (j > 0) ? rows[i + 2][j - 1] : lftv[i + 1]; // u[x+1, y+j-1]

            const float dxf  = dn   - c;
            const float dxb  = c    - up;
            const float dyf  = rgt  - c;
            const float dyb  = c    - lft;
            const float dsbf = up_r - up;    // u[x-1,y+1] - u[x-1,y]
            const float dslf = dn_l - lft;   // u[x+1,y-1] - u[x,  y-1]

            const float invF = rsqrtf(fmaf(dxf, dxf, fmaf(dyf, dyf, EPS)));
            const float invG = rsqrtf(fmaf(dxb, dxb, fmaf(dsbf, dsbf, EPS)));
            const float invH = rsqrtf(fmaf(dslf, dslf, fmaf(dyb, dyb, EPS)));

            res[j] = (dxf + dyf) * invF - dxb * invG - dyb * invH;
        }
        float4 o;
        o.x = res[0]; o.y = res[1]; o.z = res[2]; o.w = res[3];
        *reinterpret_cast<float4*>(ob + (size_t)(x0 + i) * W + y) = o;
    }
}

extern "C" void kernel_launch(void* const* d_in, const int* in_sizes, int n_in,
                              void* d_out, int out_size) {
    const float* u = (const float*)d_in[0];
    float* out = (float*)d_out;
    const int batch = in_sizes[0] / (H * W);   // 16
    const int blocks = batch * (H / ROWS);     // 4096
    curvature_kernel<<<blocks, TPB>>>(u, out);
}

// round 7
// speedup vs baseline: 1.2686x; 1.2686x over previous
#include <cuda_runtime.h>
#include <cuda_bf16.h>

#define EPS 1e-16f
#define W 1024
#define H 1024
#define ROWS 4          // output rows per thread/block
#define TPB 256         // 256 threads * 4 px = 1024 = full row width

__global__ __launch_bounds__(TPB, 6)
void curvature_kernel(const float* __restrict__ u, float* __restrict__ out) {
    // block handles ROWS rows x full width of one batch image
    const int tile = blockIdx.x;            // b * (H/ROWS) + row-tile
    const int b    = tile >> 8;             // H/ROWS = 256 tiles per image
    const int x0   = (tile & 255) * ROWS;   // first output row
    const int t    = threadIdx.x;
    const int y    = t * 4;                 // first output col (float4 granule)

    const float* ub = u   + (size_t)b * (H * W);
    float*       ob = out + (size_t)b * (H * W);

    // edge exchange buffers: [k][t]
    //   edgeL[k][t] = rows[k+1][3]  (right edge of quad, = left neighbor of t+1)
    //   edgeR[k][t] = rows[k][0]    (left edge of quad,  = right neighbor of t-1)
    __shared__ float edgeL[ROWS + 1][TPB];
    __shared__ float edgeR[ROWS + 1][TPB];

    // ---- 6 row-vectors (rows x0-1 .. x0+4) at col y, reflect-clamped in x ----
    float rows[ROWS + 2][4];
    #pragma unroll
    for (int i = 0; i < ROWS + 2; ++i) {
        int r = x0 - 1 + i;
        r = (r < 0) ? 1 : ((r >= H) ? (H - 2) : r);
        float4 v = *reinterpret_cast<const float4*>(ub + (size_t)r * W + y);
        rows[i][0] = v.x; rows[i][1] = v.y; rows[i][2] = v.z; rows[i][3] = v.w;
    }

    // ---- publish quad edges (fire-and-forget STS), one barrier, read sides ----
    #pragma unroll
    for (int k = 0; k <= ROWS; ++k) {
        edgeL[k][t] = rows[k + 1][3];
        edgeR[k][t] = rows[k][0];
    }
    __syncthreads();

    const int tm = (t == 0)       ? 0       : (t - 1);
    const int tp = (t == TPB - 1) ? TPB - 1 : (t + 1);
    float lftv[ROWS + 1], rgtv[ROWS + 1];
    #pragma unroll
    for (int k = 0; k <= ROWS; ++k) {
        // u[reflect(x0+k), y-1]; image edge (y==0) reflects to col 1 = own reg
        float l = edgeL[k][tm];
        lftv[k] = (t == 0) ? rows[k + 1][1] : l;
        // u[reflect(x0-1+k), y+4]; image edge (y+4==W) reflects to col W-2 = own reg
        float r = edgeR[k][tp];
        rgtv[k] = (t == TPB - 1) ? rows[k][2] : r;
    }

    // ---- compute ROWS x 4 outputs ----
    #pragma unroll
    for (int i = 0; i < ROWS; ++i) {
        float res[4];
        #pragma unroll
        for (int j = 0; j < 4; ++j) {
            const float c    = rows[i + 1][j];                        // u[x, y+j]
            const float up   = rows[i][j];                            // u[x-1, y+j]
            const float dn   = rows[i + 2][j];                        // u[x+1, y+j]
            const float rgt  = (j < 3) ? rows[i + 1][j + 1] : rgtv[i + 1]; // u[x, y+j+1]
            const float lft  = (j > 0) ? rows[i + 1][j - 1] : lftv[i];     // u[x, y+j-1]
            const float up_r = (j < 3) ? rows[i][j + 1]     : rgtv[i];     // u[x-1, y+j+1]
            const float dn_l = (j > 0) ? rows[i + 2][j - 1] : lftv[i + 1]; // u[x+1, y+j-1]

            const float dxf  = dn   - c;
            const float dxb  = c    - up;
            const float dyf  = rgt  - c;
            const float dyb  = c    - lft;
            const float dsbf = up_r - up;    // u[x-1,y+1] - u[x-1,y]
            const float dslf = dn_l - lft;   // u[x+1,y-1] - u[x,  y-1]

            const float invF = rsqrtf(fmaf(dxf, dxf, fmaf(dyf, dyf, EPS)));
            const float invG = rsqrtf(fmaf(dxb, dxb, fmaf(dsbf, dsbf, EPS)));
            const float invH = rsqrtf(fmaf(dslf, dslf, fmaf(dyb, dyb, EPS)));

            res[j] = (dxf + dyf) * invF - dxb * invG - dyb * invH;
        }
        float4 o;
        o.x = res[0]; o.y = res[1]; o.z = res[2]; o.w = res[3];
        *reinterpret_cast<float4*>(ob + (size_t)(x0 + i) * W + y) = o;
    }
}

extern "C" void kernel_launch(void* const* d_in, const int* in_sizes, int n_in,
                              void* d_out, int out_size) {
    const float* u = (const float*)d_in[0];
    float* out = (float*)d_out;
    const int batch = in_sizes[0] / (H * W);   // 16
    const int blocks = batch * (H / ROWS);     // 4096
    curvature_kernel<<<blocks, TPB>>>(u, out);
}